// round 1
// baseline (speedup 1.0000x reference)
#include <cuda_runtime.h>
#include <cuda_bf16.h>
#include <math.h>

// ---------------- problem constants ----------------
#define B_   2
#define NQ_  8192
#define DM_  256
#define NH_  6
#define DH_  64
#define NL_  3
#define NP_  9
#define NHD_ (NH_*DH_)            // 384
#define NOFF_ (NH_*NL_*NP_*2)     // 324
#define NATT_ (NH_*NL_*NP_)       // 162
#define TOTHW_ 10080              // 7680+1920+480

// level tables
__device__ __constant__ int   c_W[3]   = {160, 80, 40};
__device__ __constant__ int   c_H[3]   = {48, 24, 12};
__device__ __constant__ int   c_OFF[3] = {0, 7680, 9600};
__device__ __constant__ float c_SX[3]  = {160.f/1280.f, 80.f/1280.f, 40.f/1280.f};
__device__ __constant__ float c_SY[3]  = {48.f/384.f, 24.f/384.f, 12.f/384.f};

// ---------------- scratch (no allocs allowed) ----------------
__device__ float g_v   [(size_t)B_ * TOTHW_ * NHD_];   // value projection, [b][pix][h*64+d]
__device__ float g_off [(size_t)B_ * NQ_ * NOFF_];
__device__ float g_attn[(size_t)B_ * NQ_ * NATT_];
__device__ float g_mid [(size_t)B_ * NQ_ * NHD_];

// ---------------- generic SGEMM: C = op(A)[M,K] @ W[K,N] + bias ----------------
// transLD==0 : A row-major [M,K]; optional A2 added elementwise (q = x + pe fusion)
// transLD>0  : A[m,k] = A[k*transLD + m]  (feature maps: [K, M] layout)
#define BM 64
#define BN 64
#define BK 16

__global__ __launch_bounds__(256)
void sgemm_kernel(const float* __restrict__ A, const float* __restrict__ A2,
                  const float* __restrict__ W, const float* __restrict__ bias,
                  float* __restrict__ C,
                  int M, int N, int K, int transLD,
                  long strideA, long strideC)
{
    __shared__ float As[BK][BM + 4];
    __shared__ float Bs[BK][BN + 4];

    const int bz = blockIdx.z;
    const float* Ab  = A + (long)bz * strideA;
    const float* A2b = A2 ? (A2 + (long)bz * strideA) : nullptr;
    float* Cb = C + (long)bz * strideC;

    const int m0 = blockIdx.y * BM;
    const int n0 = blockIdx.x * BN;
    const int tid = threadIdx.x;
    const int tx = tid & 15;
    const int ty = tid >> 4;

    float acc[4][4] = {};

    for (int k0 = 0; k0 < K; k0 += BK) {
        // ---- load A tile ----
        if (transLD == 0) {
            int m_l = tid >> 2;
            int k_l = (tid & 3) * 4;
            int m = m0 + m_l;
            float4 v = make_float4(0.f, 0.f, 0.f, 0.f);
            if (m < M) {
                v = *reinterpret_cast<const float4*>(&Ab[(long)m * K + k0 + k_l]);
                if (A2b) {
                    float4 v2 = *reinterpret_cast<const float4*>(&A2b[(long)m * K + k0 + k_l]);
                    v.x += v2.x; v.y += v2.y; v.z += v2.z; v.w += v2.w;
                }
            }
            As[k_l + 0][m_l] = v.x;
            As[k_l + 1][m_l] = v.y;
            As[k_l + 2][m_l] = v.z;
            As[k_l + 3][m_l] = v.w;
        } else {
            #pragma unroll
            for (int i = 0; i < 4; i++) {
                int idx = tid + i * 256;
                int k_l = idx >> 6;
                int m_l = idx & 63;
                int m = m0 + m_l;
                As[k_l][m_l] = (m < M) ? Ab[(long)(k0 + k_l) * transLD + m] : 0.f;
            }
        }
        // ---- load B tile ----
        #pragma unroll
        for (int i = 0; i < 4; i++) {
            int idx = tid + i * 256;
            int k_l = idx >> 6;
            int n_l = idx & 63;
            int n = n0 + n_l;
            Bs[k_l][n_l] = (n < N) ? W[(long)(k0 + k_l) * N + n] : 0.f;
        }
        __syncthreads();

        #pragma unroll
        for (int k = 0; k < BK; k++) {
            float4 a4 = *reinterpret_cast<const float4*>(&As[k][ty * 4]);
            float4 b4 = *reinterpret_cast<const float4*>(&Bs[k][tx * 4]);
            float a[4] = {a4.x, a4.y, a4.z, a4.w};
            float b[4] = {b4.x, b4.y, b4.z, b4.w};
            #pragma unroll
            for (int i = 0; i < 4; i++)
                #pragma unroll
                for (int j = 0; j < 4; j++)
                    acc[i][j] += a[i] * b[j];
        }
        __syncthreads();
    }

    #pragma unroll
    for (int i = 0; i < 4; i++) {
        int m = m0 + ty * 4 + i;
        if (m >= M) continue;
        #pragma unroll
        for (int j = 0; j < 4; j++) {
            int n = n0 + tx * 4 + j;
            if (n < N) Cb[(long)m * N + n] = acc[i][j] + bias[n];
        }
    }
}

// ---------------- sampler: projection + softmax + bilinear gather + attn-weighted sum ----------------
// block = 384 threads (h = tid/64, d = tid%64); grid = (NQ, B)
__global__ __launch_bounds__(384)
void sample_kernel(const float* __restrict__ coor,
                   const float* __restrict__ cam2img,
                   const float* __restrict__ lidar2cam)
{
    const int q = blockIdx.x;
    const int b = blockIdx.y;
    const int tid = threadIdx.x;
    const int h = tid >> 6;
    const int d = tid & 63;

    __shared__ float s_uv[2];
    __shared__ float s_logit[NH_][NL_*NP_];
    __shared__ float s_w[NH_][NL_*NP_];
    __shared__ int   s_idx[NH_][NL_*NP_][4];
    __shared__ float s_bw[NH_][NL_*NP_][4];

    // ---- projection (one thread) ----
    if (tid == 0) {
        const float* L  = lidar2cam + b * 16;
        const float* Kc = cam2img + b * 16;
        float p0 = coor[((long)b * NQ_ + q) * 3 + 0];
        float p1 = coor[((long)b * NQ_ + q) * 3 + 1];
        float p2 = coor[((long)b * NQ_ + q) * 3 + 2];
        float pc[3], pr[3];
        #pragma unroll
        for (int i = 0; i < 3; i++)
            pc[i] = L[i*4+0]*p0 + L[i*4+1]*p1 + L[i*4+2]*p2 + L[i*4+3];
        #pragma unroll
        for (int i = 0; i < 3; i++)
            pr[i] = Kc[i*4+0]*pc[0] + Kc[i*4+1]*pc[1] + Kc[i*4+2]*pc[2] + Kc[i*4+3];
        s_uv[0] = pr[0] / pr[2];
        s_uv[1] = pr[1] / pr[2];
    }
    __syncthreads();

    const long bq = (long)b * NQ_ + q;

    // ---- per-sample precompute by 27 threads per head ----
    if (d < NL_*NP_) {
        const int j = d;
        const int l = j / NP_;
        const int p = j - l * NP_;

        s_logit[h][j] = g_attn[bq * NATT_ + h * (NL_*NP_) + j];

        const float* offp = &g_off[bq * NOFF_ + h * (NL_*NP_*2) + l * (NP_*2) + p * 2];
        float px = s_uv[0] * c_SX[l] + offp[0] - 0.5f;
        float py = s_uv[1] * c_SY[l] + offp[1] - 0.5f;
        float x0 = floorf(px), y0 = floorf(py);
        float fx = px - x0, fy = py - y0;
        const int wl = c_W[l], hl = c_H[l];
        const int base_l = b * TOTHW_ + c_OFF[l];

        #pragma unroll
        for (int c = 0; c < 4; c++) {
            int dx = c & 1, dy = c >> 1;
            float xi = x0 + dx, yi = y0 + dy;
            bool valid = (xi >= 0.f) && (xi < (float)wl) && (yi >= 0.f) && (yi < (float)hl);
            float wgt = (dx ? fx : 1.f - fx) * (dy ? fy : 1.f - fy);
            float xc = fminf(fmaxf(xi, 0.f), (float)(wl - 1));
            float yc = fminf(fmaxf(yi, 0.f), (float)(hl - 1));
            int pix = (int)yc * wl + (int)xc;
            s_idx[h][j][c] = (base_l + pix) * NHD_ + h * DH_;
            s_bw[h][j][c]  = valid ? wgt : 0.f;
        }
    }
    __syncthreads();

    // ---- softmax: exp with max subtraction ----
    if (d < NL_*NP_) {
        float mx = -1e30f;
        #pragma unroll
        for (int jj = 0; jj < NL_*NP_; jj++) mx = fmaxf(mx, s_logit[h][jj]);
        s_w[h][d] = expf(s_logit[h][d] - mx);
    }
    __syncthreads();

    float sum = 0.f;
    #pragma unroll
    for (int jj = 0; jj < NL_*NP_; jj++) sum += s_w[h][jj];
    const float rsum = 1.f / sum;

    // ---- gather + accumulate ----
    float acc = 0.f;
    #pragma unroll 3
    for (int j = 0; j < NL_*NP_; j++) {
        float aw = s_w[h][j] * rsum;
        const int*   id = s_idx[h][j];
        const float* bw = s_bw[h][j];
        float s = bw[0] * g_v[id[0] + d]
                + bw[1] * g_v[id[1] + d]
                + bw[2] * g_v[id[2] + d]
                + bw[3] * g_v[id[3] + d];
        acc += aw * s;
    }
    g_mid[bq * NHD_ + h * DH_ + d] = acc;
}

// ---------------- host launcher ----------------
extern "C" void kernel_launch(void* const* d_in, const int* in_sizes, int n_in,
                              void* d_out, int out_size)
{
    const float* x         = (const float*)d_in[0];
    const float* pe        = (const float*)d_in[1];
    const float* coor      = (const float*)d_in[2];
    const float* cam2img   = (const float*)d_in[3];
    const float* lidar2cam = (const float*)d_in[4];
    const float* feat0     = (const float*)d_in[5];
    const float* feat1     = (const float*)d_in[6];
    const float* feat2     = (const float*)d_in[7];
    const float* W_value   = (const float*)d_in[8];
    const float* b_value   = (const float*)d_in[9];
    const float* W_off     = (const float*)d_in[10];
    const float* b_off     = (const float*)d_in[11];
    const float* W_attn    = (const float*)d_in[12];
    const float* b_attn    = (const float*)d_in[13];
    const float* W_out     = (const float*)d_in[14];
    const float* b_out     = (const float*)d_in[15];
    float* out = (float*)d_out;

    float *pv, *poff, *pattn, *pmid;
    cudaGetSymbolAddress((void**)&pv, g_v);
    cudaGetSymbolAddress((void**)&poff, g_off);
    cudaGetSymbolAddress((void**)&pattn, g_attn);
    cudaGetSymbolAddress((void**)&pmid, g_mid);

    const int hw[3]  = {7680, 1920, 480};
    const int off[3] = {0, 7680, 9600};
    const float* feats[3] = {feat0, feat1, feat2};

    // 1) value projection per level (A transposed: feat is [B, 256, hw])
    for (int l = 0; l < 3; l++) {
        dim3 grid((NHD_ + BN - 1) / BN, (hw[l] + BM - 1) / BM, B_);
        sgemm_kernel<<<grid, 256>>>(feats[l], nullptr, W_value, b_value,
                                    pv + (long)off[l] * NHD_,
                                    hw[l], NHD_, DM_, /*transLD=*/hw[l],
                                    (long)DM_ * hw[l], (long)TOTHW_ * NHD_);
    }

    // 2) offsets GEMM: (x+pe) @ W_off
    {
        dim3 grid((NOFF_ + BN - 1) / BN, (B_ * NQ_ + BM - 1) / BM, 1);
        sgemm_kernel<<<grid, 256>>>(x, pe, W_off, b_off, poff,
                                    B_ * NQ_, NOFF_, DM_, 0, 0, 0);
    }

    // 3) attention logits GEMM: (x+pe) @ W_attn
    {
        dim3 grid((NATT_ + BN - 1) / BN, (B_ * NQ_ + BM - 1) / BM, 1);
        sgemm_kernel<<<grid, 256>>>(x, pe, W_attn, b_attn, pattn,
                                    B_ * NQ_, NATT_, DM_, 0, 0, 0);
    }

    // 4) projection + softmax + bilinear sampling + weighted accumulation
    {
        dim3 grid(NQ_, B_);
        sample_kernel<<<grid, 384>>>(coor, cam2img, lidar2cam);
    }

    // 5) output GEMM: mid @ W_out + b_out
    {
        dim3 grid((DM_ + BN - 1) / BN, (B_ * NQ_ + BM - 1) / BM, 1);
        sgemm_kernel<<<grid, 256>>>(pmid, nullptr, W_out, b_out, out,
                                    B_ * NQ_, DM_, NHD_, 0, 0, 0);
    }
}

// round 2
// speedup vs baseline: 1.5678x; 1.5678x over previous
#include <cuda_runtime.h>
#include <cuda_bf16.h>
#include <math.h>
#include <stdint.h>

// ---------------- problem constants ----------------
#define B_   2
#define NQ_  8192
#define DM_  256
#define NH_  6
#define DH_  64
#define NL_  3
#define NP_  9
#define NHD_ (NH_*DH_)            // 384
#define NOFF_ (NH_*NL_*NP_*2)     // 324
#define NATT_ (NH_*NL_*NP_)       // 162
#define TOTHW_ 10080              // 7680+1920+480

// level tables
__device__ __constant__ int   c_W[3]   = {160, 80, 40};
__device__ __constant__ int   c_H[3]   = {48, 24, 12};
__device__ __constant__ int   c_OFF[3] = {0, 7680, 9600};
__device__ __constant__ float c_SX[3]  = {160.f/1280.f, 80.f/1280.f, 40.f/1280.f};
__device__ __constant__ float c_SY[3]  = {48.f/384.f, 24.f/384.f, 12.f/384.f};

// ---------------- scratch (no allocs allowed) ----------------
__device__ float g_v   [(size_t)B_ * TOTHW_ * NHD_];   // value projection, [b][pix][h*64+d]
__device__ float g_off [(size_t)B_ * NQ_ * NOFF_];
__device__ float g_attn[(size_t)B_ * NQ_ * NATT_];
__device__ float g_mid [(size_t)B_ * NQ_ * NHD_];

// ================= tensor-core GEMM (bf16 3-term split, fp32 accurate) =================
// C[M,N] = op(A)[M,K] @ W[K,N] + bias
// transLD==0 : A row-major [M,K] (+ optional A2 added elementwise)
// transLD>0  : A[m,k] = A[k*transLD + m]   (feature maps [K, M])
// Block tile 128x64, BK=32, 8 warps (4m x 2n), warp tile 32x32, mma.m16n8k16.bf16.

__device__ __forceinline__ void split2(float f0, float f1, uint32_t& hi, uint32_t& lo) {
    __nv_bfloat16 h0 = __float2bfloat16_rn(f0);
    __nv_bfloat16 h1 = __float2bfloat16_rn(f1);
    float r0 = f0 - __bfloat162float(h0);
    float r1 = f1 - __bfloat162float(h1);
    __nv_bfloat16 l0 = __float2bfloat16_rn(r0);
    __nv_bfloat16 l1 = __float2bfloat16_rn(r1);
    __nv_bfloat162 H; H.x = h0; H.y = h1;
    __nv_bfloat162 L; L.x = l0; L.y = l1;
    hi = *reinterpret_cast<uint32_t*>(&H);
    lo = *reinterpret_cast<uint32_t*>(&L);
}

#define MMA16816(d, a, b) \
  asm volatile("mma.sync.aligned.m16n8k16.row.col.f32.bf16.bf16.f32 " \
    "{%0,%1,%2,%3},{%4,%5,%6,%7},{%8,%9},{%0,%1,%2,%3};" \
    : "+f"((d)[0]), "+f"((d)[1]), "+f"((d)[2]), "+f"((d)[3]) \
    : "r"((a)[0]), "r"((a)[1]), "r"((a)[2]), "r"((a)[3]), "r"((b)[0]), "r"((b)[1]))

#define AS_ 136
#define BS_ 72
#define A_WORDS (16*AS_)            // 2176
#define B_WORDS (16*BS_)            // 1152
#define STAGE_W (2*A_WORDS + 2*B_WORDS)   // 6656 words
#define SMEM_BYTES (2*STAGE_W*4)          // 53248

__global__ __launch_bounds__(256, 2)
void mma_gemm(const float* __restrict__ A, const float* __restrict__ A2,
              const float* __restrict__ W, const float* __restrict__ bias,
              float* __restrict__ C, int M, int N, int K, int transLD,
              long strideA, long strideC)
{
    extern __shared__ uint32_t sm[];

    const int bz = blockIdx.z;
    const float* Ab  = A + (long)bz * strideA;
    const float* A2b = A2 ? (A2 + (long)bz * strideA) : nullptr;
    float* Cb = C + (long)bz * strideC;

    const int m0 = blockIdx.y * 128;
    const int n0 = blockIdx.x * 64;
    const int tid  = threadIdx.x;
    const int lane = tid & 31;
    const int warp = tid >> 5;
    const int wm = warp & 3, wn = warp >> 2;
    const int r = lane >> 2, cc = lane & 3;

    float acc[2][4][4];
    #pragma unroll
    for (int i = 0; i < 2; i++)
        #pragma unroll
        for (int j = 0; j < 4; j++)
            #pragma unroll
            for (int t = 0; t < 4; t++) acc[i][j][t] = 0.f;

    const int nst = K >> 5;
    float4 pa[4];
    float  pb[8];

    // ---- global load of k-tile kt into registers ----
    #define GLOAD(kt) { \
      const int k0g = (kt) << 5; \
      if (transLD == 0) { \
        _Pragma("unroll") for (int p = 0; p < 4; p++) { \
          int m = (tid >> 3) + p * 32; \
          int kq = (tid & 7) * 4; \
          float4 v = make_float4(0.f,0.f,0.f,0.f); \
          if (m0 + m < M) { \
            v = *(const float4*)&Ab[(long)(m0 + m) * K + k0g + kq]; \
            if (A2b) { \
              float4 u = *(const float4*)&A2b[(long)(m0 + m) * K + k0g + kq]; \
              v.x += u.x; v.y += u.y; v.z += u.z; v.w += u.w; \
            } \
          } \
          pa[p] = v; \
        } \
      } else { \
        _Pragma("unroll") for (int p = 0; p < 2; p++) { \
          int kp = (tid >> 5) + p * 8; \
          int ml = (tid & 31) * 4; \
          float4 v0 = make_float4(0.f,0.f,0.f,0.f), v1 = v0; \
          if (m0 + ml < M) { \
            v0 = *(const float4*)&Ab[(long)(k0g + 2*kp    ) * transLD + m0 + ml]; \
            v1 = *(const float4*)&Ab[(long)(k0g + 2*kp + 1) * transLD + m0 + ml]; \
          } \
          pa[p*2] = v0; pa[p*2+1] = v1; \
        } \
      } \
      { int kp = tid >> 4; int nq = (tid & 15) * 4; \
        _Pragma("unroll") for (int i = 0; i < 4; i++) { \
          int n = n0 + nq + i; \
          pb[i]   = (n < N) ? W[(long)(k0g + 2*kp    ) * N + n] : 0.f; \
          pb[4+i] = (n < N) ? W[(long)(k0g + 2*kp + 1) * N + n] : 0.f; \
        } } \
    }

    // ---- convert + store registers into smem stage buf ----
    #define GSTORE(buf) { \
      uint32_t* Ah = sm + (buf) * STAGE_W; \
      uint32_t* Al = Ah + A_WORDS; \
      uint32_t* Bh = Al + A_WORDS; \
      uint32_t* Bl = Bh + B_WORDS; \
      if (transLD == 0) { \
        _Pragma("unroll") for (int p = 0; p < 4; p++) { \
          int m = (tid >> 3) + p * 32; \
          int kp0 = (tid & 7) * 2; \
          uint32_t h0,l0,h1,l1; \
          split2(pa[p].x, pa[p].y, h0, l0); \
          split2(pa[p].z, pa[p].w, h1, l1); \
          Ah[kp0*AS_ + m] = h0; Ah[(kp0+1)*AS_ + m] = h1; \
          Al[kp0*AS_ + m] = l0; Al[(kp0+1)*AS_ + m] = l1; \
        } \
      } else { \
        _Pragma("unroll") for (int p = 0; p < 2; p++) { \
          int kp = (tid >> 5) + p * 8; \
          int ml = (tid & 31) * 4; \
          const float* f0 = (const float*)&pa[p*2]; \
          const float* f1 = (const float*)&pa[p*2+1]; \
          uint32_t h[4], l[4]; \
          _Pragma("unroll") for (int i = 0; i < 4; i++) split2(f0[i], f1[i], h[i], l[i]); \
          *(uint4*)&Ah[kp*AS_ + ml] = make_uint4(h[0],h[1],h[2],h[3]); \
          *(uint4*)&Al[kp*AS_ + ml] = make_uint4(l[0],l[1],l[2],l[3]); \
        } \
      } \
      { int kp = tid >> 4; int nq = (tid & 15) * 4; \
        uint32_t h[4], l[4]; \
        _Pragma("unroll") for (int i = 0; i < 4; i++) split2(pb[i], pb[4+i], h[i], l[i]); \
        *(uint4*)&Bh[kp*BS_ + nq] = make_uint4(h[0],h[1],h[2],h[3]); \
        *(uint4*)&Bl[kp*BS_ + nq] = make_uint4(l[0],l[1],l[2],l[3]); \
      } \
    }

    // ---- compute a stage ----
    #define COMPUTE(buf) { \
      const uint32_t* Ah = sm + (buf) * STAGE_W; \
      const uint32_t* Al = Ah + A_WORDS; \
      const uint32_t* Bh = Al + A_WORDS; \
      const uint32_t* Bl = Bh + B_WORDS; \
      _Pragma("unroll") for (int kk = 0; kk < 2; kk++) { \
        const int kb = kk * 8 + cc; \
        uint32_t ah[2][4], al[2][4], bh[4][2], bl[4][2]; \
        _Pragma("unroll") for (int mt = 0; mt < 2; mt++) { \
          int mrow = wm * 32 + mt * 16 + r; \
          ah[mt][0] = Ah[kb*AS_ + mrow];     ah[mt][1] = Ah[kb*AS_ + mrow + 8]; \
          ah[mt][2] = Ah[(kb+4)*AS_ + mrow]; ah[mt][3] = Ah[(kb+4)*AS_ + mrow + 8]; \
          al[mt][0] = Al[kb*AS_ + mrow];     al[mt][1] = Al[kb*AS_ + mrow + 8]; \
          al[mt][2] = Al[(kb+4)*AS_ + mrow]; al[mt][3] = Al[(kb+4)*AS_ + mrow + 8]; \
        } \
        _Pragma("unroll") for (int nt = 0; nt < 4; nt++) { \
          int ncol = wn * 32 + nt * 8 + r; \
          bh[nt][0] = Bh[kb*BS_ + ncol]; bh[nt][1] = Bh[(kb+4)*BS_ + ncol]; \
          bl[nt][0] = Bl[kb*BS_ + ncol]; bl[nt][1] = Bl[(kb+4)*BS_ + ncol]; \
        } \
        _Pragma("unroll") for (int mt = 0; mt < 2; mt++) \
          _Pragma("unroll") for (int nt = 0; nt < 4; nt++) { \
            MMA16816(acc[mt][nt], ah[mt], bh[nt]); \
            MMA16816(acc[mt][nt], al[mt], bh[nt]); \
            MMA16816(acc[mt][nt], ah[mt], bl[nt]); \
          } \
      } \
    }

    GLOAD(0);
    GSTORE(0);
    __syncthreads();

    for (int s = 0; s < nst; s++) {
        if (s + 1 < nst) GLOAD(s + 1);
        COMPUTE(s & 1);
        if (s + 1 < nst) GSTORE((s + 1) & 1);
        __syncthreads();
    }

    // ---- epilogue ----
    #pragma unroll
    for (int mt = 0; mt < 2; mt++) {
        int m = m0 + wm * 32 + mt * 16 + r;
        #pragma unroll
        for (int nt = 0; nt < 4; nt++) {
            int n = n0 + wn * 32 + nt * 8 + cc * 2;
            const float* d = acc[mt][nt];
            if (m < M) {
                if (n < N)     Cb[(long)m * N + n]     = d[0] + bias[n];
                if (n + 1 < N) Cb[(long)m * N + n + 1] = d[1] + bias[n + 1];
            }
            if (m + 8 < M) {
                if (n < N)     Cb[(long)(m + 8) * N + n]     = d[2] + bias[n];
                if (n + 1 < N) Cb[(long)(m + 8) * N + n + 1] = d[3] + bias[n + 1];
            }
        }
    }
}

// ---------------- sampler: projection + softmax + bilinear gather + attn-weighted sum ----------------
__global__ __launch_bounds__(384)
void sample_kernel(const float* __restrict__ coor,
                   const float* __restrict__ cam2img,
                   const float* __restrict__ lidar2cam)
{
    const int q = blockIdx.x;
    const int b = blockIdx.y;
    const int tid = threadIdx.x;
    const int h = tid >> 6;
    const int d = tid & 63;

    __shared__ float s_uv[2];
    __shared__ float s_logit[NH_][NL_*NP_];
    __shared__ float s_w[NH_][NL_*NP_];
    __shared__ int   s_idx[NH_][NL_*NP_][4];
    __shared__ float s_bw[NH_][NL_*NP_][4];

    if (tid == 0) {
        const float* L  = lidar2cam + b * 16;
        const float* Kc = cam2img + b * 16;
        float p0 = coor[((long)b * NQ_ + q) * 3 + 0];
        float p1 = coor[((long)b * NQ_ + q) * 3 + 1];
        float p2 = coor[((long)b * NQ_ + q) * 3 + 2];
        float pc[3], pr[3];
        #pragma unroll
        for (int i = 0; i < 3; i++)
            pc[i] = L[i*4+0]*p0 + L[i*4+1]*p1 + L[i*4+2]*p2 + L[i*4+3];
        #pragma unroll
        for (int i = 0; i < 3; i++)
            pr[i] = Kc[i*4+0]*pc[0] + Kc[i*4+1]*pc[1] + Kc[i*4+2]*pc[2] + Kc[i*4+3];
        s_uv[0] = pr[0] / pr[2];
        s_uv[1] = pr[1] / pr[2];
    }
    __syncthreads();

    const long bq = (long)b * NQ_ + q;

    if (d < NL_*NP_) {
        const int j = d;
        const int l = j / NP_;
        const int p = j - l * NP_;

        s_logit[h][j] = g_attn[bq * NATT_ + h * (NL_*NP_) + j];

        const float* offp = &g_off[bq * NOFF_ + h * (NL_*NP_*2) + l * (NP_*2) + p * 2];
        float px = s_uv[0] * c_SX[l] + offp[0] - 0.5f;
        float py = s_uv[1] * c_SY[l] + offp[1] - 0.5f;
        float x0 = floorf(px), y0 = floorf(py);
        float fx = px - x0, fy = py - y0;
        const int wl = c_W[l], hl = c_H[l];
        const int base_l = b * TOTHW_ + c_OFF[l];

        #pragma unroll
        for (int c = 0; c < 4; c++) {
            int dx = c & 1, dy = c >> 1;
            float xi = x0 + dx, yi = y0 + dy;
            bool valid = (xi >= 0.f) && (xi < (float)wl) && (yi >= 0.f) && (yi < (float)hl);
            float wgt = (dx ? fx : 1.f - fx) * (dy ? fy : 1.f - fy);
            float xc = fminf(fmaxf(xi, 0.f), (float)(wl - 1));
            float yc = fminf(fmaxf(yi, 0.f), (float)(hl - 1));
            int pix = (int)yc * wl + (int)xc;
            s_idx[h][j][c] = (base_l + pix) * NHD_ + h * DH_;
            s_bw[h][j][c]  = valid ? wgt : 0.f;
        }
    }
    __syncthreads();

    if (d < NL_*NP_) {
        float mx = -1e30f;
        #pragma unroll
        for (int jj = 0; jj < NL_*NP_; jj++) mx = fmaxf(mx, s_logit[h][jj]);
        s_w[h][d] = expf(s_logit[h][d] - mx);
    }
    __syncthreads();

    float sum = 0.f;
    #pragma unroll
    for (int jj = 0; jj < NL_*NP_; jj++) sum += s_w[h][jj];
    const float rsum = 1.f / sum;

    float acc = 0.f;
    #pragma unroll 3
    for (int j = 0; j < NL_*NP_; j++) {
        float aw = s_w[h][j] * rsum;
        const int*   id = s_idx[h][j];
        const float* bw = s_bw[h][j];
        float s = bw[0] * g_v[id[0] + d]
                + bw[1] * g_v[id[1] + d]
                + bw[2] * g_v[id[2] + d]
                + bw[3] * g_v[id[3] + d];
        acc += aw * s;
    }
    g_mid[bq * NHD_ + h * DH_ + d] = acc;
}

// ---------------- host launcher ----------------
extern "C" void kernel_launch(void* const* d_in, const int* in_sizes, int n_in,
                              void* d_out, int out_size)
{
    const float* x         = (const float*)d_in[0];
    const float* pe        = (const float*)d_in[1];
    const float* coor      = (const float*)d_in[2];
    const float* cam2img   = (const float*)d_in[3];
    const float* lidar2cam = (const float*)d_in[4];
    const float* feat0     = (const float*)d_in[5];
    const float* feat1     = (const float*)d_in[6];
    const float* feat2     = (const float*)d_in[7];
    const float* W_value   = (const float*)d_in[8];
    const float* b_value   = (const float*)d_in[9];
    const float* W_off     = (const float*)d_in[10];
    const float* b_off     = (const float*)d_in[11];
    const float* W_attn    = (const float*)d_in[12];
    const float* b_attn    = (const float*)d_in[13];
    const float* W_out     = (const float*)d_in[14];
    const float* b_out     = (const float*)d_in[15];
    float* out = (float*)d_out;

    float *pv, *poff, *pattn, *pmid;
    cudaGetSymbolAddress((void**)&pv, g_v);
    cudaGetSymbolAddress((void**)&poff, g_off);
    cudaGetSymbolAddress((void**)&pattn, g_attn);
    cudaGetSymbolAddress((void**)&pmid, g_mid);

    cudaFuncSetAttribute(mma_gemm, cudaFuncAttributeMaxDynamicSharedMemorySize, SMEM_BYTES);

    const int hw[3]  = {7680, 1920, 480};
    const int off[3] = {0, 7680, 9600};
    const float* feats[3] = {feat0, feat1, feat2};

    // 1) value projection per level (A transposed: feat is [B, 256, hw])
    for (int l = 0; l < 3; l++) {
        dim3 grid((NHD_ + 63) / 64, (hw[l] + 127) / 128, B_);
        mma_gemm<<<grid, 256, SMEM_BYTES>>>(feats[l], nullptr, W_value, b_value,
                                            pv + (long)off[l] * NHD_,
                                            hw[l], NHD_, DM_, /*transLD=*/hw[l],
                                            (long)DM_ * hw[l], (long)TOTHW_ * NHD_);
    }

    // 2) offsets GEMM: (x+pe) @ W_off
    {
        dim3 grid((NOFF_ + 63) / 64, (B_ * NQ_ + 127) / 128, 1);
        mma_gemm<<<grid, 256, SMEM_BYTES>>>(x, pe, W_off, b_off, poff,
                                            B_ * NQ_, NOFF_, DM_, 0, 0, 0);
    }

    // 3) attention logits GEMM: (x+pe) @ W_attn
    {
        dim3 grid((NATT_ + 63) / 64, (B_ * NQ_ + 127) / 128, 1);
        mma_gemm<<<grid, 256, SMEM_BYTES>>>(x, pe, W_attn, b_attn, pattn,
                                            B_ * NQ_, NATT_, DM_, 0, 0, 0);
    }

    // 4) projection + softmax + bilinear sampling + weighted accumulation
    {
        dim3 grid(NQ_, B_);
        sample_kernel<<<grid, 384>>>(coor, cam2img, lidar2cam);
    }

    // 5) output GEMM: mid @ W_out + b_out
    {
        dim3 grid((DM_ + 63) / 64, (B_ * NQ_ + 127) / 128, 1);
        mma_gemm<<<grid, 256, SMEM_BYTES>>>(pmid, nullptr, W_out, b_out, out,
                                            B_ * NQ_, DM_, NHD_, 0, 0, 0);
    }
}

// round 3
// speedup vs baseline: 1.5747x; 1.0044x over previous
#include <cuda_runtime.h>
#include <cuda_bf16.h>
#include <math.h>
#include <stdint.h>

// ---------------- problem constants ----------------
#define B_   2
#define NQ_  8192
#define DM_  256
#define NH_  6
#define DH_  64
#define NL_  3
#define NP_  9
#define NHD_ (NH_*DH_)            // 384
#define NOFF_ (NH_*NL_*NP_*2)     // 324
#define NATT_ (NH_*NL_*NP_)       // 162
#define TOTHW_ 10080              // 7680+1920+480

// level tables
__device__ __constant__ int   c_W[3]   = {160, 80, 40};
__device__ __constant__ int   c_H[3]   = {48, 24, 12};
__device__ __constant__ int   c_OFF[3] = {0, 7680, 9600};
__device__ __constant__ float c_SX[3]  = {160.f/1280.f, 80.f/1280.f, 40.f/1280.f};
__device__ __constant__ float c_SY[3]  = {48.f/384.f, 24.f/384.f, 12.f/384.f};

// ---------------- scratch (no allocs allowed) ----------------
__device__ float g_v   [(size_t)B_ * TOTHW_ * NHD_];   // value projection, [b][pix][h*64+d]
__device__ float g_off [(size_t)B_ * NQ_ * NOFF_];
__device__ float g_attn[(size_t)B_ * NQ_ * NATT_];
__device__ float g_mid [(size_t)B_ * NQ_ * NHD_];

// ================= tensor-core GEMM (bf16 3-term split, fp32 accurate) =================
// C[M,N] = op(A)[M,K] @ W[K,N] + bias
// transLD==0 : A row-major [M,K] (+ optional A2 added elementwise)
// transLD>0  : A[m,k] = A[k*transLD + m]   (feature maps [K, M])
// Block tile 128x64, BK=32, 8 warps (4m x 2n), warp tile 32x32, mma.m16n8k16.bf16.

__device__ __forceinline__ void split2(float f0, float f1, uint32_t& hi, uint32_t& lo) {
    __nv_bfloat16 h0 = __float2bfloat16_rn(f0);
    __nv_bfloat16 h1 = __float2bfloat16_rn(f1);
    float r0 = f0 - __bfloat162float(h0);
    float r1 = f1 - __bfloat162float(h1);
    __nv_bfloat16 l0 = __float2bfloat16_rn(r0);
    __nv_bfloat16 l1 = __float2bfloat16_rn(r1);
    __nv_bfloat162 H; H.x = h0; H.y = h1;
    __nv_bfloat162 L; L.x = l0; L.y = l1;
    hi = *reinterpret_cast<uint32_t*>(&H);
    lo = *reinterpret_cast<uint32_t*>(&L);
}

#define MMA16816(d, a, b) \
  asm volatile("mma.sync.aligned.m16n8k16.row.col.f32.bf16.bf16.f32 " \
    "{%0,%1,%2,%3},{%4,%5,%6,%7},{%8,%9},{%0,%1,%2,%3};" \
    : "+f"((d)[0]), "+f"((d)[1]), "+f"((d)[2]), "+f"((d)[3]) \
    : "r"((a)[0]), "r"((a)[1]), "r"((a)[2]), "r"((a)[3]), "r"((b)[0]), "r"((b)[1]))

#define AS_ 136
#define BS_ 72
#define A_WORDS (16*AS_)            // 2176
#define B_WORDS (16*BS_)            // 1152
#define STAGE_W (2*A_WORDS + 2*B_WORDS)   // 6656 words
#define SMEM_BYTES (2*STAGE_W*4)          // 53248

__global__ __launch_bounds__(256, 2)
void mma_gemm(const float* __restrict__ A, const float* __restrict__ A2,
              const float* __restrict__ W, const float* __restrict__ bias,
              float* __restrict__ C, int M, int N, int K, int transLD,
              long strideA, long strideC)
{
    extern __shared__ uint32_t sm[];

    const int bz = blockIdx.z;
    const float* Ab  = A + (long)bz * strideA;
    const float* A2b = A2 ? (A2 + (long)bz * strideA) : nullptr;
    float* Cb = C + (long)bz * strideC;

    const int m0 = blockIdx.y * 128;
    const int n0 = blockIdx.x * 64;
    const int tid  = threadIdx.x;
    const int lane = tid & 31;
    const int warp = tid >> 5;
    const int wm = warp & 3, wn = warp >> 2;
    const int r = lane >> 2, cc = lane & 3;

    float acc[2][4][4];
    #pragma unroll
    for (int i = 0; i < 2; i++)
        #pragma unroll
        for (int j = 0; j < 4; j++)
            #pragma unroll
            for (int t = 0; t < 4; t++) acc[i][j][t] = 0.f;

    const int nst = K >> 5;
    float4 pa[4];
    float  pb[8];

    // ---- global load of k-tile kt into registers ----
    #define GLOAD(kt) { \
      const int k0g = (kt) << 5; \
      if (transLD == 0) { \
        _Pragma("unroll") for (int p = 0; p < 4; p++) { \
          int m = (tid >> 3) + p * 32; \
          int kq = (tid & 7) * 4; \
          float4 v = make_float4(0.f,0.f,0.f,0.f); \
          if (m0 + m < M) { \
            v = *(const float4*)&Ab[(long)(m0 + m) * K + k0g + kq]; \
            if (A2b) { \
              float4 u = *(const float4*)&A2b[(long)(m0 + m) * K + k0g + kq]; \
              v.x += u.x; v.y += u.y; v.z += u.z; v.w += u.w; \
            } \
          } \
          pa[p] = v; \
        } \
      } else { \
        _Pragma("unroll") for (int p = 0; p < 2; p++) { \
          int kp = (tid >> 5) + p * 8; \
          int ml = (tid & 31) * 4; \
          float4 v0 = make_float4(0.f,0.f,0.f,0.f), v1 = v0; \
          if (m0 + ml < M) { \
            v0 = *(const float4*)&Ab[(long)(k0g + 2*kp    ) * transLD + m0 + ml]; \
            v1 = *(const float4*)&Ab[(long)(k0g + 2*kp + 1) * transLD + m0 + ml]; \
          } \
          pa[p*2] = v0; pa[p*2+1] = v1; \
        } \
      } \
      { int kp = tid >> 4; int nq = (tid & 15) * 4; \
        _Pragma("unroll") for (int i = 0; i < 4; i++) { \
          int n = n0 + nq + i; \
          pb[i]   = (n < N) ? W[(long)(k0g + 2*kp    ) * N + n] : 0.f; \
          pb[4+i] = (n < N) ? W[(long)(k0g + 2*kp + 1) * N + n] : 0.f; \
        } } \
    }

    // ---- convert + store registers into smem stage buf ----
    #define GSTORE(buf) { \
      uint32_t* Ah = sm + (buf) * STAGE_W; \
      uint32_t* Al = Ah + A_WORDS; \
      uint32_t* Bh = Al + A_WORDS; \
      uint32_t* Bl = Bh + B_WORDS; \
      if (transLD == 0) { \
        _Pragma("unroll") for (int p = 0; p < 4; p++) { \
          int m = (tid >> 3) + p * 32; \
          int kp0 = (tid & 7) * 2; \
          uint32_t h0,l0,h1,l1; \
          split2(pa[p].x, pa[p].y, h0, l0); \
          split2(pa[p].z, pa[p].w, h1, l1); \
          Ah[kp0*AS_ + m] = h0; Ah[(kp0+1)*AS_ + m] = h1; \
          Al[kp0*AS_ + m] = l0; Al[(kp0+1)*AS_ + m] = l1; \
        } \
      } else { \
        _Pragma("unroll") for (int p = 0; p < 2; p++) { \
          int kp = (tid >> 5) + p * 8; \
          int ml = (tid & 31) * 4; \
          const float* f0 = (const float*)&pa[p*2]; \
          const float* f1 = (const float*)&pa[p*2+1]; \
          uint32_t h[4], l[4]; \
          _Pragma("unroll") for (int i = 0; i < 4; i++) split2(f0[i], f1[i], h[i], l[i]); \
          *(uint4*)&Ah[kp*AS_ + ml] = make_uint4(h[0],h[1],h[2],h[3]); \
          *(uint4*)&Al[kp*AS_ + ml] = make_uint4(l[0],l[1],l[2],l[3]); \
        } \
      } \
      { int kp = tid >> 4; int nq = (tid & 15) * 4; \
        uint32_t h[4], l[4]; \
        _Pragma("unroll") for (int i = 0; i < 4; i++) split2(pb[i], pb[4+i], h[i], l[i]); \
        *(uint4*)&Bh[kp*BS_ + nq] = make_uint4(h[0],h[1],h[2],h[3]); \
        *(uint4*)&Bl[kp*BS_ + nq] = make_uint4(l[0],l[1],l[2],l[3]); \
      } \
    }

    // ---- compute a stage ----
    #define COMPUTE(buf) { \
      const uint32_t* Ah = sm + (buf) * STAGE_W; \
      const uint32_t* Al = Ah + A_WORDS; \
      const uint32_t* Bh = Al + A_WORDS; \
      const uint32_t* Bl = Bh + B_WORDS; \
      _Pragma("unroll") for (int kk = 0; kk < 2; kk++) { \
        const int kb = kk * 8 + cc; \
        uint32_t ah[2][4], al[2][4], bh[4][2], bl[4][2]; \
        _Pragma("unroll") for (int mt = 0; mt < 2; mt++) { \
          int mrow = wm * 32 + mt * 16 + r; \
          ah[mt][0] = Ah[kb*AS_ + mrow];     ah[mt][1] = Ah[kb*AS_ + mrow + 8]; \
          ah[mt][2] = Ah[(kb+4)*AS_ + mrow]; ah[mt][3] = Ah[(kb+4)*AS_ + mrow + 8]; \
          al[mt][0] = Al[kb*AS_ + mrow];     al[mt][1] = Al[kb*AS_ + mrow + 8]; \
          al[mt][2] = Al[(kb+4)*AS_ + mrow]; al[mt][3] = Al[(kb+4)*AS_ + mrow + 8]; \
        } \
        _Pragma("unroll") for (int nt = 0; nt < 4; nt++) { \
          int ncol = wn * 32 + nt * 8 + r; \
          bh[nt][0] = Bh[kb*BS_ + ncol]; bh[nt][1] = Bh[(kb+4)*BS_ + ncol]; \
          bl[nt][0] = Bl[kb*BS_ + ncol]; bl[nt][1] = Bl[(kb+4)*BS_ + ncol]; \
        } \
        _Pragma("unroll") for (int mt = 0; mt < 2; mt++) \
          _Pragma("unroll") for (int nt = 0; nt < 4; nt++) { \
            MMA16816(acc[mt][nt], ah[mt], bh[nt]); \
            MMA16816(acc[mt][nt], al[mt], bh[nt]); \
            MMA16816(acc[mt][nt], ah[mt], bl[nt]); \
          } \
      } \
    }

    GLOAD(0);
    GSTORE(0);
    __syncthreads();

    for (int s = 0; s < nst; s++) {
        if (s + 1 < nst) GLOAD(s + 1);
        COMPUTE(s & 1);
        if (s + 1 < nst) GSTORE((s + 1) & 1);
        __syncthreads();
    }

    // ---- epilogue ----
    #pragma unroll
    for (int mt = 0; mt < 2; mt++) {
        int m = m0 + wm * 32 + mt * 16 + r;
        #pragma unroll
        for (int nt = 0; nt < 4; nt++) {
            int n = n0 + wn * 32 + nt * 8 + cc * 2;
            const float* d = acc[mt][nt];
            if (m < M) {
                if (n < N)     Cb[(long)m * N + n]     = d[0] + bias[n];
                if (n + 1 < N) Cb[(long)m * N + n + 1] = d[1] + bias[n + 1];
            }
            if (m + 8 < M) {
                if (n < N)     Cb[(long)(m + 8) * N + n]     = d[2] + bias[n];
                if (n + 1 < N) Cb[(long)(m + 8) * N + n + 1] = d[3] + bias[n + 1];
            }
        }
    }
}

// ---------------- sampler: projection + softmax + bilinear gather + attn-weighted sum ----------------
__global__ __launch_bounds__(384)
void sample_kernel(const float* __restrict__ coor,
                   const float* __restrict__ cam2img,
                   const float* __restrict__ lidar2cam)
{
    const int q = blockIdx.x;
    const int b = blockIdx.y;
    const int tid = threadIdx.x;
    const int h = tid >> 6;
    const int d = tid & 63;

    __shared__ float s_uv[2];
    __shared__ float s_logit[NH_][NL_*NP_];
    __shared__ float s_w[NH_][NL_*NP_];
    __shared__ int   s_idx[NH_][NL_*NP_][4];
    __shared__ float s_bw[NH_][NL_*NP_][4];

    if (tid == 0) {
        const float* L  = lidar2cam + b * 16;
        const float* Kc = cam2img + b * 16;
        float p0 = coor[((long)b * NQ_ + q) * 3 + 0];
        float p1 = coor[((long)b * NQ_ + q) * 3 + 1];
        float p2 = coor[((long)b * NQ_ + q) * 3 + 2];
        float pc[3], pr[3];
        #pragma unroll
        for (int i = 0; i < 3; i++)
            pc[i] = L[i*4+0]*p0 + L[i*4+1]*p1 + L[i*4+2]*p2 + L[i*4+3];
        #pragma unroll
        for (int i = 0; i < 3; i++)
            pr[i] = Kc[i*4+0]*pc[0] + Kc[i*4+1]*pc[1] + Kc[i*4+2]*pc[2] + Kc[i*4+3];
        s_uv[0] = pr[0] / pr[2];
        s_uv[1] = pr[1] / pr[2];
    }
    __syncthreads();

    const long bq = (long)b * NQ_ + q;

    if (d < NL_*NP_) {
        const int j = d;
        const int l = j / NP_;
        const int p = j - l * NP_;

        s_logit[h][j] = g_attn[bq * NATT_ + h * (NL_*NP_) + j];

        const float* offp = &g_off[bq * NOFF_ + h * (NL_*NP_*2) + l * (NP_*2) + p * 2];
        float px = s_uv[0] * c_SX[l] + offp[0] - 0.5f;
        float py = s_uv[1] * c_SY[l] + offp[1] - 0.5f;
        float x0 = floorf(px), y0 = floorf(py);
        float fx = px - x0, fy = py - y0;
        const int wl = c_W[l], hl = c_H[l];
        const int base_l = b * TOTHW_ + c_OFF[l];

        #pragma unroll
        for (int c = 0; c < 4; c++) {
            int dx = c & 1, dy = c >> 1;
            float xi = x0 + dx, yi = y0 + dy;
            bool valid = (xi >= 0.f) && (xi < (float)wl) && (yi >= 0.f) && (yi < (float)hl);
            float wgt = (dx ? fx : 1.f - fx) * (dy ? fy : 1.f - fy);
            float xc = fminf(fmaxf(xi, 0.f), (float)(wl - 1));
            float yc = fminf(fmaxf(yi, 0.f), (float)(hl - 1));
            int pix = (int)yc * wl + (int)xc;
            s_idx[h][j][c] = (base_l + pix) * NHD_ + h * DH_;
            s_bw[h][j][c]  = valid ? wgt : 0.f;
        }
    }
    __syncthreads();

    if (d < NL_*NP_) {
        float mx = -1e30f;
        #pragma unroll
        for (int jj = 0; jj < NL_*NP_; jj++) mx = fmaxf(mx, s_logit[h][jj]);
        s_w[h][d] = expf(s_logit[h][d] - mx);
    }
    __syncthreads();

    float sum = 0.f;
    #pragma unroll
    for (int jj = 0; jj < NL_*NP_; jj++) sum += s_w[h][jj];
    const float rsum = 1.f / sum;

    float acc = 0.f;
    #pragma unroll 3
    for (int j = 0; j < NL_*NP_; j++) {
        float aw = s_w[h][j] * rsum;
        const int*   id = s_idx[h][j];
        const float* bw = s_bw[h][j];
        float s = bw[0] * g_v[id[0] + d]
                + bw[1] * g_v[id[1] + d]
                + bw[2] * g_v[id[2] + d]
                + bw[3] * g_v[id[3] + d];
        acc += aw * s;
    }
    g_mid[bq * NHD_ + h * DH_ + d] = acc;
}

// ---------------- host launcher ----------------
extern "C" void kernel_launch(void* const* d_in, const int* in_sizes, int n_in,
                              void* d_out, int out_size)
{
    const float* x         = (const float*)d_in[0];
    const float* pe        = (const float*)d_in[1];
    const float* coor      = (const float*)d_in[2];
    const float* cam2img   = (const float*)d_in[3];
    const float* lidar2cam = (const float*)d_in[4];
    const float* feat0     = (const float*)d_in[5];
    const float* feat1     = (const float*)d_in[6];
    const float* feat2     = (const float*)d_in[7];
    const float* W_value   = (const float*)d_in[8];
    const float* b_value   = (const float*)d_in[9];
    const float* W_off     = (const float*)d_in[10];
    const float* b_off     = (const float*)d_in[11];
    const float* W_attn    = (const float*)d_in[12];
    const float* b_attn    = (const float*)d_in[13];
    const float* W_out     = (const float*)d_in[14];
    const float* b_out     = (const float*)d_in[15];
    float* out = (float*)d_out;

    float *pv, *poff, *pattn, *pmid;
    cudaGetSymbolAddress((void**)&pv, g_v);
    cudaGetSymbolAddress((void**)&poff, g_off);
    cudaGetSymbolAddress((void**)&pattn, g_attn);
    cudaGetSymbolAddress((void**)&pmid, g_mid);

    cudaFuncSetAttribute(mma_gemm, cudaFuncAttributeMaxDynamicSharedMemorySize, SMEM_BYTES);

    const int hw[3]  = {7680, 1920, 480};
    const int off[3] = {0, 7680, 9600};
    const float* feats[3] = {feat0, feat1, feat2};

    // 1) value projection per level (A transposed: feat is [B, 256, hw])
    for (int l = 0; l < 3; l++) {
        dim3 grid((NHD_ + 63) / 64, (hw[l] + 127) / 128, B_);
        mma_gemm<<<grid, 256, SMEM_BYTES>>>(feats[l], nullptr, W_value, b_value,
                                            pv + (long)off[l] * NHD_,
                                            hw[l], NHD_, DM_, /*transLD=*/hw[l],
                                            (long)DM_ * hw[l], (long)TOTHW_ * NHD_);
    }

    // 2) offsets GEMM: (x+pe) @ W_off
    {
        dim3 grid((NOFF_ + 63) / 64, (B_ * NQ_ + 127) / 128, 1);
        mma_gemm<<<grid, 256, SMEM_BYTES>>>(x, pe, W_off, b_off, poff,
                                            B_ * NQ_, NOFF_, DM_, 0, 0, 0);
    }

    // 3) attention logits GEMM: (x+pe) @ W_attn
    {
        dim3 grid((NATT_ + 63) / 64, (B_ * NQ_ + 127) / 128, 1);
        mma_gemm<<<grid, 256, SMEM_BYTES>>>(x, pe, W_attn, b_attn, pattn,
                                            B_ * NQ_, NATT_, DM_, 0, 0, 0);
    }

    // 4) projection + softmax + bilinear sampling + weighted accumulation
    {
        dim3 grid(NQ_, B_);
        sample_kernel<<<grid, 384>>>(coor, cam2img, lidar2cam);
    }

    // 5) output GEMM: mid @ W_out + b_out
    {
        dim3 grid((DM_ + 63) / 64, (B_ * NQ_ + 127) / 128, 1);
        mma_gemm<<<grid, 256, SMEM_BYTES>>>(pmid, nullptr, W_out, b_out, out,
                                            B_ * NQ_, DM_, NHD_, 0, 0, 0);
    }
}